// round 2
// baseline (speedup 1.0000x reference)
#include <cuda_runtime.h>
#include <math.h>

#define BATCH   8
#define SEQ     2048
#define DIM     256
#define HEADS   8
#define BQ      64
#define BK      64
#define NTHR    256
#define QS      257           // padded row stride for q/k smem tiles (conflict-free)

// Scratch (allocation-free rule: __device__ globals)
__device__ float g_Weff[DIM * DIM];                 // 256 KB
__device__ float g_Y[BATCH * SEQ * DIM];            // 16 MB

// ---------------------------------------------------------------------------
// W_eff[d_out][d_in] = sum_h W_o[d_out, h*DIM + d_in]
// ---------------------------------------------------------------------------
__global__ void weff_kernel(const float* __restrict__ Wo) {
    int t = blockIdx.x * blockDim.x + threadIdx.x;   // 0 .. 65535
    int dout = t >> 8;
    int din  = t & 255;
    float s = 0.f;
#pragma unroll
    for (int h = 0; h < HEADS; h++)
        s += Wo[(size_t)dout * (DIM * HEADS) + h * DIM + din];
    g_Weff[t] = s;
}

// ---------------------------------------------------------------------------
// Attention: per (batch, 64-query tile). Scores clipped to [-10,10] so no
// online max is needed: w = exp(clip(s)), normalize by row sum at the end.
// y[q] = (1/(q+1)) * sum_k w_qk e_k / sum_k w_qk, written to g_Y.
// ---------------------------------------------------------------------------
__global__ __launch_bounds__(NTHR, 1)
void attn_kernel(const float* __restrict__ e, const float* __restrict__ p) {
    extern __shared__ float sm[];
    float* qs   = sm;                     // [BQ][QS]  q tile, natural layout
    float* ks   = qs + BQ * QS;           // [BK][QS]  k tile
    float* es   = ks + BK * QS;           // [BK][DIM] e tile (natural, stride 256)
    float* ws   = es + BK * DIM;          // [BK][BQ]  exp-weights, transposed
    float* rp   = ws + BK * BQ;           // [16][BQ]  rowsum partials
    float* rtot = rp + 16 * BQ;           // [BQ]

    const int tid = threadIdx.x;
    const int ty  = tid >> 4;             // 0..15 : query group (4 rows)
    const int tx  = tid & 15;             // 0..15 : key group (GEMM1) / dim group (GEMM2)
    const int qt  = (int)(gridDim.x - 1) - (int)blockIdx.x;  // heavy tiles first
    const int b   = blockIdx.y;
    const int q0  = qt * BQ;

    const float* pb = p + (size_t)b * (SEQ + 1) * DIM;
    const float* eb = e + (size_t)b * SEQ * DIM;

    // Load Q tile once: q row r = p[b, q0+r+1, :]
    for (int idx = tid; idx < BQ * DIM / 4; idx += NTHR) {
        int r  = idx >> 6;                // 64 float4 per row
        int c4 = idx & 63;
        float4 v = *reinterpret_cast<const float4*>(pb + (size_t)(q0 + r + 1) * DIM + c4 * 4);
        float* dst = qs + r * QS + c4 * 4;
        dst[0] = v.x; dst[1] = v.y; dst[2] = v.z; dst[3] = v.w;
    }

    float yacc[4][16];
#pragma unroll
    for (int i = 0; i < 4; i++)
#pragma unroll
        for (int j = 0; j < 16; j++) yacc[i][j] = 0.f;
    float rs[4] = {0.f, 0.f, 0.f, 0.f};

    __syncthreads();

    const int ntiles = qt + 1;            // causal: key tiles 0..qt
    for (int kt = 0; kt < ntiles; kt++) {
        const int k0 = kt * BK;

        // Load K tile (k row r = p[b, k0+r, :]) and E tile
        for (int idx = tid; idx < BK * DIM / 4; idx += NTHR) {
            int r  = idx >> 6;
            int c4 = idx & 63;
            float4 v = *reinterpret_cast<const float4*>(pb + (size_t)(k0 + r) * DIM + c4 * 4);
            float* dst = ks + r * QS + c4 * 4;
            dst[0] = v.x; dst[1] = v.y; dst[2] = v.z; dst[3] = v.w;
            float4 w = *reinterpret_cast<const float4*>(eb + (size_t)(k0 + r) * DIM + c4 * 4);
            *reinterpret_cast<float4*>(es + r * DIM + c4 * 4) = w;
        }
        __syncthreads();

        // GEMM1: 64x64 scores, 4x4 per thread
        float sacc[4][4];
#pragma unroll
        for (int i = 0; i < 4; i++)
#pragma unroll
            for (int j = 0; j < 4; j++) sacc[i][j] = 0.f;

        const float* qrow = qs + (ty * 4) * QS;
        const float* krow = ks + (tx * 4) * QS;
#pragma unroll 8
        for (int kk = 0; kk < DIM; kk++) {
            float a0 = qrow[kk];
            float a1 = qrow[QS + kk];
            float a2 = qrow[2 * QS + kk];
            float a3 = qrow[3 * QS + kk];
            float b0 = krow[kk];
            float b1 = krow[QS + kk];
            float b2 = krow[2 * QS + kk];
            float b3 = krow[3 * QS + kk];
            sacc[0][0] += a0 * b0; sacc[0][1] += a0 * b1; sacc[0][2] += a0 * b2; sacc[0][3] += a0 * b3;
            sacc[1][0] += a1 * b0; sacc[1][1] += a1 * b1; sacc[1][2] += a1 * b2; sacc[1][3] += a1 * b3;
            sacc[2][0] += a2 * b0; sacc[2][1] += a2 * b1; sacc[2][2] += a2 * b2; sacc[2][3] += a2 * b3;
            sacc[3][0] += a3 * b0; sacc[3][1] += a3 * b1; sacc[3][2] += a3 * b2; sacc[3][3] += a3 * b3;
        }

        // Epilogue: scale, clip, causal mask, exp; write transposed, track rowsums
#pragma unroll
        for (int i = 0; i < 4; i++) {
            int qg = q0 + ty * 4 + i;
#pragma unroll
            for (int j = 0; j < 4; j++) {
                int kg = k0 + tx * 4 + j;
                float s = sacc[i][j] * 0.0625f;            // 1/sqrt(256)
                s = fminf(10.f, fmaxf(-10.f, s));
                float w = (kg <= qg) ? __expf(s) : 0.f;
                ws[(tx * 4 + j) * BQ + (ty * 4 + i)] = w;
                rs[i] += w;
            }
        }
        __syncthreads();

        // GEMM2: yacc[m][d] += sum_k2 ws[k2][m] * es[k2][d]; 4 queries x 16 dims per thread
        const int dbase = tx * 16;
#pragma unroll 2
        for (int k2 = 0; k2 < BK; k2++) {
            float4 a = *reinterpret_cast<const float4*>(ws + k2 * BQ + ty * 4);
            const float* er = es + k2 * DIM + dbase;
            float4 b0 = *reinterpret_cast<const float4*>(er);
            float4 b1 = *reinterpret_cast<const float4*>(er + 4);
            float4 b2 = *reinterpret_cast<const float4*>(er + 8);
            float4 b3 = *reinterpret_cast<const float4*>(er + 12);
            const float av[4] = {a.x, a.y, a.z, a.w};
#pragma unroll
            for (int i = 0; i < 4; i++) {
                float ai = av[i];
                yacc[i][0]  += ai * b0.x; yacc[i][1]  += ai * b0.y; yacc[i][2]  += ai * b0.z; yacc[i][3]  += ai * b0.w;
                yacc[i][4]  += ai * b1.x; yacc[i][5]  += ai * b1.y; yacc[i][6]  += ai * b1.z; yacc[i][7]  += ai * b1.w;
                yacc[i][8]  += ai * b2.x; yacc[i][9]  += ai * b2.y; yacc[i][10] += ai * b2.z; yacc[i][11] += ai * b2.w;
                yacc[i][12] += ai * b3.x; yacc[i][13] += ai * b3.y; yacc[i][14] += ai * b3.z; yacc[i][15] += ai * b3.w;
            }
        }
        __syncthreads();
    }

    // Reduce row sums across the 16 key-group threads
#pragma unroll
    for (int i = 0; i < 4; i++) rp[tx * BQ + ty * 4 + i] = rs[i];
    __syncthreads();
    if (tid < BQ) {
        float s = 0.f;
#pragma unroll
        for (int x = 0; x < 16; x++) s += rp[x * BQ + tid];
        rtot[tid] = s;
    }
    __syncthreads();

    // Normalize (softmax denom * 1/(q+1)) and write y
#pragma unroll
    for (int i = 0; i < 4; i++) {
        int qg = q0 + ty * 4 + i;
        float scale = 1.f / (rtot[ty * 4 + i] * (float)(qg + 1));
        float* yrow = g_Y + ((size_t)b * SEQ + qg) * DIM + tx * 16;
#pragma unroll
        for (int v = 0; v < 4; v++) {
            float4 o;
            o.x = yacc[i][v * 4 + 0] * scale;
            o.y = yacc[i][v * 4 + 1] * scale;
            o.z = yacc[i][v * 4 + 2] * scale;
            o.w = yacc[i][v * 4 + 3] * scale;
            *reinterpret_cast<float4*>(yrow + v * 4) = o;
        }
    }
}

// ---------------------------------------------------------------------------
// Projection: out[m][n] = sum_k Y[m][k] * W_eff[n][k]   (M=16384, N=256, K=256)
// ---------------------------------------------------------------------------
#define PK 32
#define PS 33
__global__ __launch_bounds__(256, 2)
void proj_kernel(float* __restrict__ out) {
    __shared__ float as[64 * PS];   // Y tile  [m][kk]
    __shared__ float bs[64 * PS];   // Weff tile [n][kk]
    const int tid = threadIdx.x;
    const int ty = tid >> 4;
    const int tx = tid & 15;
    const int m0 = blockIdx.x * 64;
    const int n0 = blockIdx.y * 64;

    float acc[4][4];
#pragma unroll
    for (int i = 0; i < 4; i++)
#pragma unroll
        for (int j = 0; j < 4; j++) acc[i][j] = 0.f;

    for (int kt = 0; kt < DIM / PK; kt++) {
        const int kk0 = kt * PK;
        for (int idx = tid; idx < 64 * PK / 4; idx += 256) {
            int r  = idx >> 3;            // 8 float4 per row
            int c4 = idx & 7;
            float4 v = *reinterpret_cast<const float4*>(g_Y + (size_t)(m0 + r) * DIM + kk0 + c4 * 4);
            float* da = as + r * PS + c4 * 4;
            da[0] = v.x; da[1] = v.y; da[2] = v.z; da[3] = v.w;
            float4 w = *reinterpret_cast<const float4*>(g_Weff + (size_t)(n0 + r) * DIM + kk0 + c4 * 4);
            float* db = bs + r * PS + c4 * 4;
            db[0] = w.x; db[1] = w.y; db[2] = w.z; db[3] = w.w;
        }
        __syncthreads();

#pragma unroll
        for (int kk = 0; kk < PK; kk++) {
            float a0 = as[(ty * 4 + 0) * PS + kk];
            float a1 = as[(ty * 4 + 1) * PS + kk];
            float a2 = as[(ty * 4 + 2) * PS + kk];
            float a3 = as[(ty * 4 + 3) * PS + kk];
            float b0 = bs[(tx * 4 + 0) * PS + kk];
            float b1 = bs[(tx * 4 + 1) * PS + kk];
            float b2 = bs[(tx * 4 + 2) * PS + kk];
            float b3 = bs[(tx * 4 + 3) * PS + kk];
            acc[0][0] += a0 * b0; acc[0][1] += a0 * b1; acc[0][2] += a0 * b2; acc[0][3] += a0 * b3;
            acc[1][0] += a1 * b0; acc[1][1] += a1 * b1; acc[1][2] += a1 * b2; acc[1][3] += a1 * b3;
            acc[2][0] += a2 * b0; acc[2][1] += a2 * b1; acc[2][2] += a2 * b2; acc[2][3] += a2 * b3;
            acc[3][0] += a3 * b0; acc[3][1] += a3 * b1; acc[3][2] += a3 * b2; acc[3][3] += a3 * b3;
        }
        __syncthreads();
    }

#pragma unroll
    for (int i = 0; i < 4; i++) {
        float4 o;
        o.x = acc[i][0]; o.y = acc[i][1]; o.z = acc[i][2]; o.w = acc[i][3];
        *reinterpret_cast<float4*>(out + (size_t)(m0 + ty * 4 + i) * DIM + n0 + tx * 4) = o;
    }
}

// ---------------------------------------------------------------------------
extern "C" void kernel_launch(void* const* d_in, const int* in_sizes, int n_in,
                              void* d_out, int out_size) {
    const float *e = nullptr, *p = nullptr, *wo = nullptr;
    for (int i = 0; i < n_in; i++) {
        if      (in_sizes[i] == BATCH * SEQ * DIM)       e  = (const float*)d_in[i];
        else if (in_sizes[i] == BATCH * (SEQ + 1) * DIM) p  = (const float*)d_in[i];
        else if (in_sizes[i] == DIM * DIM * HEADS)       wo = (const float*)d_in[i];
    }

    const int smem_attn = (2 * BQ * QS + BK * DIM + BK * BQ + 16 * BQ + BQ) * (int)sizeof(float);
    cudaFuncSetAttribute(attn_kernel, cudaFuncAttributeMaxDynamicSharedMemorySize, smem_attn);

    weff_kernel<<<DIM * DIM / NTHR, NTHR>>>(wo);
    attn_kernel<<<dim3(SEQ / BQ, BATCH), NTHR, smem_attn>>>(e, p);
    proj_kernel<<<dim3(BATCH * SEQ / 64, DIM / 64), 256>>>((float*)d_out);
}

// round 4
// speedup vs baseline: 2.2339x; 2.2339x over previous
#include <cuda_runtime.h>
#include <cuda_bf16.h>
#include <cstdint>

#define BATCH 8
#define SEQ   2048
#define DIM   256
#define HEADS 8
#define BQ 64
#define BK 64
#define NTHR 256

// ---- smem byte offsets ----
#define OFF_QH 0
#define OFF_QL 32768
#define OFF_KH 65536
#define OFF_KL 98304
#define OFF_EH 131072
#define OFF_EL 163840
#define OFF_PH 196608
#define OFF_PL 204800
#define OFF_RS 212992
#define SMEM_TOTAL (OFF_RS + 256)
// reuse after key loop:
#define OFF_YH OFF_QH
#define OFF_YL OFF_QL
#define OFF_WH OFF_KH
#define OFF_WL OFF_KL

__device__ __align__(16) unsigned short g_Wh[DIM * DIM];
__device__ __align__(16) unsigned short g_Wl[DIM * DIM];

// ---- helpers ----
__device__ __forceinline__ uint32_t smem_u32(const void* p) {
    uint32_t a;
    asm("{ .reg .u64 t; cvta.to.shared.u64 t, %1; cvt.u32.u64 %0, t; }" : "=r"(a) : "l"(p));
    return a;
}
__device__ __forceinline__ void ldsm4(uint32_t addr, uint32_t& r0, uint32_t& r1, uint32_t& r2, uint32_t& r3) {
    asm volatile("ldmatrix.sync.aligned.m8n8.x4.shared.b16 {%0,%1,%2,%3}, [%4];"
                 : "=r"(r0), "=r"(r1), "=r"(r2), "=r"(r3) : "r"(addr));
}
__device__ __forceinline__ void ldsm4t(uint32_t addr, uint32_t& r0, uint32_t& r1, uint32_t& r2, uint32_t& r3) {
    asm volatile("ldmatrix.sync.aligned.m8n8.x4.trans.shared.b16 {%0,%1,%2,%3}, [%4];"
                 : "=r"(r0), "=r"(r1), "=r"(r2), "=r"(r3) : "r"(addr));
}
__device__ __forceinline__ void mma16816(float* c, uint32_t a0, uint32_t a1, uint32_t a2, uint32_t a3,
                                         uint32_t b0, uint32_t b1) {
    asm volatile("mma.sync.aligned.m16n8k16.row.col.f32.bf16.bf16.f32 "
                 "{%0,%1,%2,%3}, {%4,%5,%6,%7}, {%8,%9}, {%0,%1,%2,%3};"
                 : "+f"(c[0]), "+f"(c[1]), "+f"(c[2]), "+f"(c[3])
                 : "r"(a0), "r"(a1), "r"(a2), "r"(a3), "r"(b0), "r"(b1));
}
// split x -> hi bf16 + lo bf16; pack col pairs into b32 (low half = first col)
__device__ __forceinline__ void split2(float x0, float x1, unsigned& hp, unsigned& lp) {
    __nv_bfloat16 h0 = __float2bfloat16_rn(x0);
    __nv_bfloat16 h1 = __float2bfloat16_rn(x1);
    __nv_bfloat16 l0 = __float2bfloat16_rn(x0 - __bfloat162float(h0));
    __nv_bfloat16 l1 = __float2bfloat16_rn(x1 - __bfloat162float(h1));
    hp = (unsigned)__bfloat16_as_ushort(h0) | ((unsigned)__bfloat16_as_ushort(h1) << 16);
    lp = (unsigned)__bfloat16_as_ushort(l0) | ((unsigned)__bfloat16_as_ushort(l1) << 16);
}
#define SWZ(row, colb) ((uint32_t)(colb) ^ (((uint32_t)(row) & 7u) << 4))

// 512B-row tile (K-dim 256 bf16): store 4 consecutive cols (hi/lo)
__device__ __forceinline__ void store_split4_512(char* bh, char* bl, int row, int col, float4 v) {
    unsigned h0, l0, h1, l1;
    split2(v.x, v.y, h0, l0);
    split2(v.z, v.w, h1, l1);
    uint32_t off = (uint32_t)row * 512u + SWZ(row, col * 2);
    *(uint32_t*)(bh + off) = h0; *(uint32_t*)(bh + off + 4) = h1;
    *(uint32_t*)(bl + off) = l0; *(uint32_t*)(bl + off + 4) = l1;
}

// ---------------------------------------------------------------------------
// W_eff[n][k] = sum_h W_o[n, h*DIM + k], split to bf16 hi/lo
// ---------------------------------------------------------------------------
__global__ void weff_kernel(const float* __restrict__ Wo) {
    int t = blockIdx.x * blockDim.x + threadIdx.x;
    int dout = t >> 8, din = t & 255;
    float s = 0.f;
#pragma unroll
    for (int h = 0; h < HEADS; h++)
        s += Wo[(size_t)dout * (DIM * HEADS) + h * DIM + din];
    __nv_bfloat16 hh = __float2bfloat16_rn(s);
    g_Wh[t] = __bfloat16_as_ushort(hh);
    g_Wl[t] = __bfloat16_as_ushort(__float2bfloat16_rn(s - __bfloat162float(hh)));
}

// ---------------------------------------------------------------------------
// Fused attention + projection, mma.sync bf16 split-precision (bf16x3).
// CTA = (batch, 64-query tile), 256 threads (8 warps).
// ---------------------------------------------------------------------------
__global__ __launch_bounds__(NTHR, 1)
void attn_kernel(const float* __restrict__ e, const float* __restrict__ p,
                 float* __restrict__ out) {
    extern __shared__ char smem[];
    const uint32_t sb = smem_u32(smem);
    const int tid  = threadIdx.x;
    const int lane = tid & 31;
    const int wid  = tid >> 5;
    const int mw   = wid & 3;      // 16-row m-tile
    const int nw   = wid >> 2;     // S: 32-col slice; AV/proj: 128-dim slice
    const int qt   = 31 - (int)blockIdx.x;   // heavy tiles first
    const int b    = blockIdx.y;
    const int q0   = qt * BQ;
    const float* pb = p + (size_t)b * (SEQ + 1) * DIM;
    const float* eb = e + (size_t)b * SEQ * DIM;
    float* rowsum  = (float*)(smem + OFF_RS);

    if (tid < BQ) rowsum[tid] = 0.f;

    // ---- load + split Q (rows: p[b, q0+r+1, :]) ----
    {
        const int r  = tid >> 2;
        const int cb = (tid & 3) * 64;
        const float* qrow = pb + (size_t)(q0 + r + 1) * DIM + cb;
#pragma unroll
        for (int i = 0; i < 16; i++) {
            float4 v = *(const float4*)(qrow + i * 4);
            store_split4_512(smem + OFF_QH, smem + OFF_QL, r, cb + i * 4, v);
        }
    }
    __syncthreads();

    float yacc[16][4];
#pragma unroll
    for (int i = 0; i < 16; i++)
#pragma unroll
        for (int j = 0; j < 4; j++) yacc[i][j] = 0.f;
    float rs0 = 0.f, rs1 = 0.f;
    const int row0 = mw * 16 + (lane >> 2);           // this thread's C-frag rows
    const int qg0 = q0 + row0, qg1 = qg0 + 8;

    // ---- key-tile loop ----
    for (int kt = 0; kt <= qt; kt++) {
        const int k0 = kt * BK;
        __syncthreads();   // prev AV done before overwriting K/E

        // load + split K tile [64x256] and E tile [64x256]
        {
            const int r  = tid >> 2;
            const int cb = (tid & 3) * 64;
            const float* krow = pb + (size_t)(k0 + r) * DIM + cb;
            const float* erow = eb + (size_t)(k0 + r) * DIM + cb;
#pragma unroll
            for (int i = 0; i < 16; i++) {
                float4 v = *(const float4*)(krow + i * 4);
                store_split4_512(smem + OFF_KH, smem + OFF_KL, r, cb + i * 4, v);
                float4 w = *(const float4*)(erow + i * 4);
                store_split4_512(smem + OFF_EH, smem + OFF_EL, r, cb + i * 4, w);
            }
        }
        __syncthreads();

        // ---- S GEMM: S[64,64] = Q*K^T (bf16x3), warp: rows mw*16+, cols nw*32+ ----
        float sacc[4][4];
#pragma unroll
        for (int i = 0; i < 4; i++)
#pragma unroll
            for (int j = 0; j < 4; j++) sacc[i][j] = 0.f;

#pragma unroll
        for (int ks = 0; ks < 16; ks++) {
            // A frags (Q hi/lo)
            const int ar = mw * 16 + (lane & 15);
            const uint32_t acb = (uint32_t)(ks * 32 + ((lane >> 4) << 4));
            const uint32_t aoff = (uint32_t)ar * 512u + SWZ(ar, acb);
            uint32_t qh0, qh1, qh2, qh3, ql0, ql1, ql2, ql3;
            ldsm4(sb + OFF_QH + aoff, qh0, qh1, qh2, qh3);
            ldsm4(sb + OFF_QL + aoff, ql0, ql1, ql2, ql3);
#pragma unroll
            for (int pt = 0; pt < 2; pt++) {
                const int key = nw * 32 + pt * 16 + (lane & 7) + ((lane >> 4) << 3);
                const uint32_t kb = (uint32_t)(ks * 32 + (((lane >> 3) & 1) << 4));
                const uint32_t koff = (uint32_t)key * 512u + SWZ(key, kb);
                uint32_t kh0, kh1, kh2, kh3, kl0, kl1, kl2, kl3;
                ldsm4(sb + OFF_KH + koff, kh0, kh1, kh2, kh3);
                ldsm4(sb + OFF_KL + koff, kl0, kl1, kl2, kl3);
                mma16816(sacc[2 * pt],     qh0, qh1, qh2, qh3, kh0, kh1);
                mma16816(sacc[2 * pt],     qh0, qh1, qh2, qh3, kl0, kl1);
                mma16816(sacc[2 * pt],     ql0, ql1, ql2, ql3, kh0, kh1);
                mma16816(sacc[2 * pt + 1], qh0, qh1, qh2, qh3, kh2, kh3);
                mma16816(sacc[2 * pt + 1], qh0, qh1, qh2, qh3, kl2, kl3);
                mma16816(sacc[2 * pt + 1], ql0, ql1, ql2, ql3, kh2, kh3);
            }
        }

        // ---- epilogue: scale, clip, mask, exp; rowsum partials; P -> smem (bf16 h/l) ----
#pragma unroll
        for (int nt = 0; nt < 4; nt++) {
            const int colL = nw * 32 + nt * 8 + (lane & 3) * 2;   // tile-local key col
            const int kgl = k0 + colL;
            float s00 = fminf(10.f, fmaxf(-10.f, sacc[nt][0] * 0.0625f));
            float s01 = fminf(10.f, fmaxf(-10.f, sacc[nt][1] * 0.0625f));
            float s10 = fminf(10.f, fmaxf(-10.f, sacc[nt][2] * 0.0625f));
            float s11 = fminf(10.f, fmaxf(-10.f, sacc[nt][3] * 0.0625f));
            float w00 = (kgl     <= qg0) ? __expf(s00) : 0.f;
            float w01 = (kgl + 1 <= qg0) ? __expf(s01) : 0.f;
            float w10 = (kgl     <= qg1) ? __expf(s10) : 0.f;
            float w11 = (kgl + 1 <= qg1) ? __expf(s11) : 0.f;
            rs0 += w00 + w01;
            rs1 += w10 + w11;
            unsigned h, l;
            uint32_t o0 = (uint32_t)row0 * 128u + SWZ(row0, colL * 2);
            split2(w00, w01, h, l);
            *(uint32_t*)(smem + OFF_PH + o0) = h;
            *(uint32_t*)(smem + OFF_PL + o0) = l;
            uint32_t o1 = (uint32_t)(row0 + 8) * 128u + SWZ(row0 + 8, colL * 2);
            split2(w10, w11, h, l);
            *(uint32_t*)(smem + OFF_PH + o1) = h;
            *(uint32_t*)(smem + OFF_PL + o1) = l;
        }
        __syncthreads();

        // ---- AV GEMM: Y[64,256] += P * E (bf16x3), warp: rows mw*16+, dims nw*128+ ----
#pragma unroll
        for (int ks = 0; ks < 4; ks++) {
            const int ar = mw * 16 + (lane & 15);
            const uint32_t acb = (uint32_t)(ks * 32 + ((lane >> 4) << 4));
            const uint32_t aoff = (uint32_t)ar * 128u + SWZ(ar, acb);
            uint32_t ph0, ph1, ph2, ph3, pl0, pl1, pl2, pl3;
            ldsm4(sb + OFF_PH + aoff, ph0, ph1, ph2, ph3);
            ldsm4(sb + OFF_PL + aoff, pl0, pl1, pl2, pl3);
#pragma unroll
            for (int pt = 0; pt < 8; pt++) {
                const int key = ks * 16 + (lane & 15);
                const uint32_t dcb = (uint32_t)((nw * 128 + pt * 16 + ((lane >> 4) << 3)) * 2);
                const uint32_t eoff = (uint32_t)key * 512u + SWZ(key, dcb);
                uint32_t eh0, eh1, eh2, eh3, el0, el1, el2, el3;
                ldsm4t(sb + OFF_EH + eoff, eh0, eh1, eh2, eh3);
                ldsm4t(sb + OFF_EL + eoff, el0, el1, el2, el3);
                mma16816(yacc[2 * pt],     ph0, ph1, ph2, ph3, eh0, eh1);
                mma16816(yacc[2 * pt],     ph0, ph1, ph2, ph3, el0, el1);
                mma16816(yacc[2 * pt],     pl0, pl1, pl2, pl3, eh0, eh1);
                mma16816(yacc[2 * pt + 1], ph0, ph1, ph2, ph3, eh2, eh3);
                mma16816(yacc[2 * pt + 1], ph0, ph1, ph2, ph3, el2, el3);
                mma16816(yacc[2 * pt + 1], pl0, pl1, pl2, pl3, eh2, eh3);
            }
        }
    }

    // ---- rowsum reduce: quad shuffle + smem atomics ----
    rs0 += __shfl_xor_sync(0xffffffffu, rs0, 1);
    rs0 += __shfl_xor_sync(0xffffffffu, rs0, 2);
    rs1 += __shfl_xor_sync(0xffffffffu, rs1, 1);
    rs1 += __shfl_xor_sync(0xffffffffu, rs1, 2);
    if ((lane & 3) == 0) {
        atomicAdd(&rowsum[row0], rs0);
        atomicAdd(&rowsum[row0 + 8], rs1);
    }
    __syncthreads();

    // ---- normalize Y and store split bf16 to smem (reuse Q area) ----
    {
        const float sc0 = 1.f / (rowsum[row0] * (float)(qg0 + 1));
        const float sc1 = 1.f / (rowsum[row0 + 8] * (float)(qg1 + 1));
#pragma unroll
        for (int nt = 0; nt < 16; nt++) {
            const int col = nw * 128 + nt * 8 + (lane & 3) * 2;
            unsigned h, l;
            uint32_t o0 = (uint32_t)row0 * 512u + SWZ(row0, col * 2);
            split2(yacc[nt][0] * sc0, yacc[nt][1] * sc0, h, l);
            *(uint32_t*)(smem + OFF_YH + o0) = h;
            *(uint32_t*)(smem + OFF_YL + o0) = l;
            uint32_t o1 = (uint32_t)(row0 + 8) * 512u + SWZ(row0 + 8, col * 2);
            split2(yacc[nt][2] * sc1, yacc[nt][3] * sc1, h, l);
            *(uint32_t*)(smem + OFF_YH + o1) = h;
            *(uint32_t*)(smem + OFF_YL + o1) = l;
        }
    }

    // ---- projection: out[64,256] = Ynorm @ Weff^T, 4 chunks of K=64 ----
    float pacc[16][4];
#pragma unroll
    for (int i = 0; i < 16; i++)
#pragma unroll
        for (int j = 0; j < 4; j++) pacc[i][j] = 0.f;

    for (int ch = 0; ch < 4; ch++) {
        __syncthreads();   // Y written (ch=0) / prev chunk consumed
        {
            const int dout = tid;
#pragma unroll
            for (int i = 0; i < 8; i++) {
                uint4 vh = *(const uint4*)(g_Wh + (size_t)dout * 256 + ch * 64 + i * 8);
                uint4 vl = *(const uint4*)(g_Wl + (size_t)dout * 256 + ch * 64 + i * 8);
                uint32_t off = (uint32_t)dout * 128u + SWZ(dout, i * 16);
                *(uint4*)(smem + OFF_WH + off) = vh;
                *(uint4*)(smem + OFF_WL + off) = vl;
            }
        }
        __syncthreads();

#pragma unroll
        for (int ks = 0; ks < 4; ks++) {
            const int ar = mw * 16 + (lane & 15);
            const uint32_t acb = (uint32_t)(ch * 128 + ks * 32 + ((lane >> 4) << 4));
            const uint32_t aoff = (uint32_t)ar * 512u + SWZ(ar, acb);
            uint32_t yh0, yh1, yh2, yh3, yl0, yl1, yl2, yl3;
            ldsm4(sb + OFF_YH + aoff, yh0, yh1, yh2, yh3);
            ldsm4(sb + OFF_YL + aoff, yl0, yl1, yl2, yl3);
#pragma unroll
            for (int pt = 0; pt < 8; pt++) {
                const int dout = nw * 128 + pt * 16 + (lane & 7) + ((lane >> 4) << 3);
                const uint32_t kb = (uint32_t)(ks * 32 + (((lane >> 3) & 1) << 4));
                const uint32_t woff = (uint32_t)dout * 128u + SWZ(dout, kb);
                uint32_t wh0, wh1, wh2, wh3, wl0, wl1, wl2, wl3;
                ldsm4(sb + OFF_WH + woff, wh0, wh1, wh2, wh3);
                ldsm4(sb + OFF_WL + woff, wl0, wl1, wl2, wl3);
                mma16816(pacc[2 * pt],     yh0, yh1, yh2, yh3, wh0, wh1);
                mma16816(pacc[2 * pt],     yh0, yh1, yh2, yh3, wl0, wl1);
                mma16816(pacc[2 * pt],     yl0, yl1, yl2, yl3, wh0, wh1);
                mma16816(pacc[2 * pt + 1], yh0, yh1, yh2, yh3, wh2, wh3);
                mma16816(pacc[2 * pt + 1], yh0, yh1, yh2, yh3, wl2, wl3);
                mma16816(pacc[2 * pt + 1], yl0, yl1, yl2, yl3, wh2, wh3);
            }
        }
    }

    // ---- write output ----
    {
        float* ob = out + (size_t)b * SEQ * DIM;
#pragma unroll
        for (int nt = 0; nt < 16; nt++) {
            const int col = nw * 128 + nt * 8 + (lane & 3) * 2;
            float2 v0 = make_float2(pacc[nt][0], pacc[nt][1]);
            float2 v1 = make_float2(pacc[nt][2], pacc[nt][3]);
            *(float2*)(ob + (size_t)qg0 * DIM + col) = v0;
            *(float2*)(ob + (size_t)qg1 * DIM + col) = v1;
        }
    }
}

// ---------------------------------------------------------------------------
extern "C" void kernel_launch(void* const* d_in, const int* in_sizes, int n_in,
                              void* d_out, int out_size) {
    const float *e = nullptr, *p = nullptr, *wo = nullptr;
    for (int i = 0; i < n_in; i++) {
        if      (in_sizes[i] == BATCH * SEQ * DIM)       e  = (const float*)d_in[i];
        else if (in_sizes[i] == BATCH * (SEQ + 1) * DIM) p  = (const float*)d_in[i];
        else if (in_sizes[i] == DIM * DIM * HEADS)       wo = (const float*)d_in[i];
    }

    cudaFuncSetAttribute(attn_kernel, cudaFuncAttributeMaxDynamicSharedMemorySize, SMEM_TOTAL);

    weff_kernel<<<DIM * DIM / NTHR, NTHR>>>(wo);
    attn_kernel<<<dim3(SEQ / BQ, BATCH), NTHR, SMEM_TOTAL>>>(e, p, (float*)d_out);
}

// round 5
// speedup vs baseline: 4.2569x; 1.9056x over previous
#include <cuda_runtime.h>
#include <cuda_bf16.h>
#include <cstdint>

#define BATCH 8
#define SEQ   2048
#define DIM   256
#define HEADS 8
#define BQ 64
#define BK 64
#define NTHR 512
#define NP (BATCH * (SEQ + 1) * DIM)
#define NE (BATCH * SEQ * DIM)

// ---- smem byte offsets ----
#define OFF_QH 0
#define OFF_QL 32768
#define OFF_KH 65536
#define OFF_KL 98304
#define OFF_EH 131072
#define OFF_EL 163840
#define OFF_PH 196608
#define OFF_PL 204800
#define OFF_RS 212992
#define SMEM_TOTAL (OFF_RS + 256)
// reuse after key loop:
#define OFF_YH OFF_QH
#define OFF_YL OFF_QL
#define OFF_WH OFF_KH
#define OFF_WL OFF_KL

// pre-split operands (bf16 bits as ushort)
__device__ __align__(16) unsigned short g_ph[NP];
__device__ __align__(16) unsigned short g_pl[NP];
__device__ __align__(16) unsigned short g_eh[NE];
__device__ __align__(16) unsigned short g_el[NE];
__device__ __align__(16) unsigned short g_Wh[DIM * DIM];
__device__ __align__(16) unsigned short g_Wl[DIM * DIM];

// ---- helpers ----
__device__ __forceinline__ uint32_t smem_u32(const void* p) {
    uint32_t a;
    asm("{ .reg .u64 t; cvta.to.shared.u64 t, %1; cvt.u32.u64 %0, t; }" : "=r"(a) : "l"(p));
    return a;
}
__device__ __forceinline__ void cp16(uint32_t dst, const void* src) {
    asm volatile("cp.async.cg.shared.global [%0], [%1], 16;" :: "r"(dst), "l"(src));
}
#define CP_COMMIT() asm volatile("cp.async.commit_group;" ::: "memory")
#define CP_WAIT0()  asm volatile("cp.async.wait_group 0;" ::: "memory")

__device__ __forceinline__ void ldsm4(uint32_t addr, uint32_t& r0, uint32_t& r1, uint32_t& r2, uint32_t& r3) {
    asm volatile("ldmatrix.sync.aligned.m8n8.x4.shared.b16 {%0,%1,%2,%3}, [%4];"
                 : "=r"(r0), "=r"(r1), "=r"(r2), "=r"(r3) : "r"(addr));
}
__device__ __forceinline__ void ldsm4t(uint32_t addr, uint32_t& r0, uint32_t& r1, uint32_t& r2, uint32_t& r3) {
    asm volatile("ldmatrix.sync.aligned.m8n8.x4.trans.shared.b16 {%0,%1,%2,%3}, [%4];"
                 : "=r"(r0), "=r"(r1), "=r"(r2), "=r"(r3) : "r"(addr));
}
__device__ __forceinline__ void mma16816(float* c, uint32_t a0, uint32_t a1, uint32_t a2, uint32_t a3,
                                         uint32_t b0, uint32_t b1) {
    asm volatile("mma.sync.aligned.m16n8k16.row.col.f32.bf16.bf16.f32 "
                 "{%0,%1,%2,%3}, {%4,%5,%6,%7}, {%8,%9}, {%0,%1,%2,%3};"
                 : "+f"(c[0]), "+f"(c[1]), "+f"(c[2]), "+f"(c[3])
                 : "r"(a0), "r"(a1), "r"(a2), "r"(a3), "r"(b0), "r"(b1));
}
__device__ __forceinline__ void split2(float x0, float x1, unsigned& hp, unsigned& lp) {
    __nv_bfloat16 h0 = __float2bfloat16_rn(x0);
    __nv_bfloat16 h1 = __float2bfloat16_rn(x1);
    __nv_bfloat16 l0 = __float2bfloat16_rn(x0 - __bfloat162float(h0));
    __nv_bfloat16 l1 = __float2bfloat16_rn(x1 - __bfloat162float(h1));
    hp = (unsigned)__bfloat16_as_ushort(h0) | ((unsigned)__bfloat16_as_ushort(h1) << 16);
    lp = (unsigned)__bfloat16_as_ushort(l0) | ((unsigned)__bfloat16_as_ushort(l1) << 16);
}
#define SWZ(row, colb) ((uint32_t)(colb) ^ (((uint32_t)(row) & 7u) << 4))

// ---------------------------------------------------------------------------
// Precompute: split p/e into hi/lo bf16
// ---------------------------------------------------------------------------
__global__ void split_pe_kernel(const float* __restrict__ p, const float* __restrict__ e) {
    int i = blockIdx.x * blockDim.x + threadIdx.x;
    if (i < NP) {
        float x = p[i];
        __nv_bfloat16 h = __float2bfloat16_rn(x);
        g_ph[i] = __bfloat16_as_ushort(h);
        g_pl[i] = __bfloat16_as_ushort(__float2bfloat16_rn(x - __bfloat162float(h)));
    }
    if (i < NE) {
        float x = e[i];
        __nv_bfloat16 h = __float2bfloat16_rn(x);
        g_eh[i] = __bfloat16_as_ushort(h);
        g_el[i] = __bfloat16_as_ushort(__float2bfloat16_rn(x - __bfloat162float(h)));
    }
}

// W_eff[n][k] = sum_h W_o[n, h*DIM + k], split
__global__ void weff_kernel(const float* __restrict__ Wo) {
    int t = blockIdx.x * blockDim.x + threadIdx.x;
    int dout = t >> 8, din = t & 255;
    float s = 0.f;
#pragma unroll
    for (int h = 0; h < HEADS; h++)
        s += Wo[(size_t)dout * (DIM * HEADS) + h * DIM + din];
    __nv_bfloat16 hh = __float2bfloat16_rn(s);
    g_Wh[t] = __bfloat16_as_ushort(hh);
    g_Wl[t] = __bfloat16_as_ushort(__float2bfloat16_rn(s - __bfloat162float(hh)));
}

// ---------------------------------------------------------------------------
// Fused attention + projection, mma.sync bf16x3. CTA = (batch, 64-query tile),
// 512 threads (16 warps: 4 m-warps x 4 n-warps).
// ---------------------------------------------------------------------------
__global__ __launch_bounds__(NTHR, 1)
void attn_kernel(float* __restrict__ out) {
    extern __shared__ char smem[];
    const uint32_t sb = smem_u32(smem);
    const int tid  = threadIdx.x;
    const int lane = tid & 31;
    const int wid  = tid >> 5;
    const int mw   = wid & 3;      // 16-row m-tile
    const int nw   = wid >> 2;     // 0..3: S 16-col slice / AV,proj 64-dim slice
    const int qt   = 31 - (int)blockIdx.x;   // heavy tiles first
    const int b    = blockIdx.y;
    const int q0   = qt * BQ;
    const unsigned short* ph = g_ph + (size_t)b * (SEQ + 1) * DIM;
    const unsigned short* pl = g_pl + (size_t)b * (SEQ + 1) * DIM;
    const unsigned short* eh = g_eh + (size_t)b * SEQ * DIM;
    const unsigned short* el = g_el + (size_t)b * SEQ * DIM;
    float* rowsum = (float*)(smem + OFF_RS);

    if (tid < BQ) rowsum[tid] = 0.f;

    // ---- Q tiles via cp.async (rows q0+1 .. q0+64) ----
    {
        const int r  = tid >> 3;
        const int s0 = tid & 7;
        const unsigned short* qh = ph + (size_t)(q0 + r + 1) * DIM;
        const unsigned short* ql = pl + (size_t)(q0 + r + 1) * DIM;
#pragma unroll
        for (int j = 0; j < 4; j++) {
            const int seg = s0 + j * 8;
            const uint32_t off = (uint32_t)r * 512u + SWZ(r, seg * 16);
            cp16(sb + OFF_QH + off, qh + seg * 8);
            cp16(sb + OFF_QL + off, ql + seg * 8);
        }
        CP_COMMIT();
    }

    float yacc[8][4];
#pragma unroll
    for (int i = 0; i < 8; i++)
#pragma unroll
        for (int j = 0; j < 4; j++) yacc[i][j] = 0.f;
    float rs0 = 0.f, rs1 = 0.f;
    const int row0 = mw * 16 + (lane >> 2);
    const int qg0 = q0 + row0, qg1 = qg0 + 8;

    CP_WAIT0();
    __syncthreads();

    // ---- key-tile loop ----
    for (int kt = 0; kt <= qt; kt++) {
        const int k0 = kt * BK;
        __syncthreads();   // prev AV done before overwriting K/E

        {   // K + E tiles via cp.async
            const int r  = tid >> 3;
            const int s0 = tid & 7;
            const unsigned short* kh = ph + (size_t)(k0 + r) * DIM;
            const unsigned short* kl = pl + (size_t)(k0 + r) * DIM;
            const unsigned short* vh = eh + (size_t)(k0 + r) * DIM;
            const unsigned short* vl = el + (size_t)(k0 + r) * DIM;
#pragma unroll
            for (int j = 0; j < 4; j++) {
                const int seg = s0 + j * 8;
                const uint32_t off = (uint32_t)r * 512u + SWZ(r, seg * 16);
                cp16(sb + OFF_KH + off, kh + seg * 8);
                cp16(sb + OFF_KL + off, kl + seg * 8);
                cp16(sb + OFF_EH + off, vh + seg * 8);
                cp16(sb + OFF_EL + off, vl + seg * 8);
            }
            CP_COMMIT();
            CP_WAIT0();
        }
        __syncthreads();

        // ---- S GEMM: warp tile 16 rows x 16 keys ----
        float sacc[2][4];
#pragma unroll
        for (int i = 0; i < 2; i++)
#pragma unroll
            for (int j = 0; j < 4; j++) sacc[i][j] = 0.f;

        const int ar = mw * 16 + (lane & 15);
        const int key = nw * 16 + (lane & 7) + ((lane >> 4) << 3);
#pragma unroll
        for (int ks = 0; ks < 16; ks++) {
            const uint32_t acb = (uint32_t)(ks * 32 + ((lane >> 4) << 4));
            const uint32_t aoff = (uint32_t)ar * 512u + SWZ(ar, acb);
            uint32_t qh0, qh1, qh2, qh3, ql0, ql1, ql2, ql3;
            ldsm4(sb + OFF_QH + aoff, qh0, qh1, qh2, qh3);
            ldsm4(sb + OFF_QL + aoff, ql0, ql1, ql2, ql3);
            const uint32_t kb = (uint32_t)(ks * 32 + (((lane >> 3) & 1) << 4));
            const uint32_t koff = (uint32_t)key * 512u + SWZ(key, kb);
            uint32_t kh0, kh1, kh2, kh3, kl0, kl1, kl2, kl3;
            ldsm4(sb + OFF_KH + koff, kh0, kh1, kh2, kh3);
            ldsm4(sb + OFF_KL + koff, kl0, kl1, kl2, kl3);
            mma16816(sacc[0], qh0, qh1, qh2, qh3, kh0, kh1);
            mma16816(sacc[0], qh0, qh1, qh2, qh3, kl0, kl1);
            mma16816(sacc[0], ql0, ql1, ql2, ql3, kh0, kh1);
            mma16816(sacc[1], qh0, qh1, qh2, qh3, kh2, kh3);
            mma16816(sacc[1], qh0, qh1, qh2, qh3, kl2, kl3);
            mma16816(sacc[1], ql0, ql1, ql2, ql3, kh2, kh3);
        }

        // ---- epilogue: scale/clip/mask/exp; rowsum partials; P -> smem ----
#pragma unroll
        for (int nt = 0; nt < 2; nt++) {
            const int colL = nw * 16 + nt * 8 + (lane & 3) * 2;
            const int kgl = k0 + colL;
            float s00 = fminf(10.f, fmaxf(-10.f, sacc[nt][0] * 0.0625f));
            float s01 = fminf(10.f, fmaxf(-10.f, sacc[nt][1] * 0.0625f));
            float s10 = fminf(10.f, fmaxf(-10.f, sacc[nt][2] * 0.0625f));
            float s11 = fminf(10.f, fmaxf(-10.f, sacc[nt][3] * 0.0625f));
            float w00 = (kgl     <= qg0) ? __expf(s00) : 0.f;
            float w01 = (kgl + 1 <= qg0) ? __expf(s01) : 0.f;
            float w10 = (kgl     <= qg1) ? __expf(s10) : 0.f;
            float w11 = (kgl + 1 <= qg1) ? __expf(s11) : 0.f;
            rs0 += w00 + w01;
            rs1 += w10 + w11;
            unsigned h, l;
            uint32_t o0 = (uint32_t)row0 * 128u + SWZ(row0, colL * 2);
            split2(w00, w01, h, l);
            *(uint32_t*)(smem + OFF_PH + o0) = h;
            *(uint32_t*)(smem + OFF_PL + o0) = l;
            uint32_t o1 = (uint32_t)(row0 + 8) * 128u + SWZ(row0 + 8, colL * 2);
            split2(w10, w11, h, l);
            *(uint32_t*)(smem + OFF_PH + o1) = h;
            *(uint32_t*)(smem + OFF_PL + o1) = l;
        }
        __syncthreads();

        // ---- AV GEMM: warp tile 16 rows x 64 dims ----
#pragma unroll
        for (int ks = 0; ks < 4; ks++) {
            const uint32_t acb = (uint32_t)(ks * 32 + ((lane >> 4) << 4));
            const uint32_t aoff = (uint32_t)ar * 128u + SWZ(ar, acb);
            uint32_t ph0, ph1, ph2, ph3, pl0, pl1, pl2, pl3;
            ldsm4(sb + OFF_PH + aoff, ph0, ph1, ph2, ph3);
            ldsm4(sb + OFF_PL + aoff, pl0, pl1, pl2, pl3);
            const int key2 = ks * 16 + (lane & 15);
#pragma unroll
            for (int grp = 0; grp < 4; grp++) {
                const uint32_t dcb = (uint32_t)((nw * 64 + grp * 16 + ((lane >> 4) << 3)) * 2);
                const uint32_t eoff = (uint32_t)key2 * 512u + SWZ(key2, dcb);
                uint32_t eh0, eh1, eh2, eh3, el0, el1, el2, el3;
                ldsm4t(sb + OFF_EH + eoff, eh0, eh1, eh2, eh3);
                ldsm4t(sb + OFF_EL + eoff, el0, el1, el2, el3);
                mma16816(yacc[2 * grp],     ph0, ph1, ph2, ph3, eh0, eh1);
                mma16816(yacc[2 * grp],     ph0, ph1, ph2, ph3, el0, el1);
                mma16816(yacc[2 * grp],     pl0, pl1, pl2, pl3, eh0, eh1);
                mma16816(yacc[2 * grp + 1], ph0, ph1, ph2, ph3, eh2, eh3);
                mma16816(yacc[2 * grp + 1], ph0, ph1, ph2, ph3, el2, el3);
                mma16816(yacc[2 * grp + 1], pl0, pl1, pl2, pl3, eh2, eh3);
            }
        }
    }

    // ---- rowsum reduce ----
    rs0 += __shfl_xor_sync(0xffffffffu, rs0, 1);
    rs0 += __shfl_xor_sync(0xffffffffu, rs0, 2);
    rs1 += __shfl_xor_sync(0xffffffffu, rs1, 1);
    rs1 += __shfl_xor_sync(0xffffffffu, rs1, 2);
    if ((lane & 3) == 0) {
        atomicAdd(&rowsum[row0], rs0);
        atomicAdd(&rowsum[row0 + 8], rs1);
    }
    __syncthreads();

    // ---- normalize Y, split bf16 to smem (reuse Q area) ----
    {
        const float sc0 = 1.f / (rowsum[row0] * (float)(qg0 + 1));
        const float sc1 = 1.f / (rowsum[row0 + 8] * (float)(qg1 + 1));
#pragma unroll
        for (int nt = 0; nt < 8; nt++) {
            const int col = nw * 64 + nt * 8 + (lane & 3) * 2;
            unsigned h, l;
            uint32_t o0 = (uint32_t)row0 * 512u + SWZ(row0, col * 2);
            split2(yacc[nt][0] * sc0, yacc[nt][1] * sc0, h, l);
            *(uint32_t*)(smem + OFF_YH + o0) = h;
            *(uint32_t*)(smem + OFF_YL + o0) = l;
            uint32_t o1 = (uint32_t)(row0 + 8) * 512u + SWZ(row0 + 8, col * 2);
            split2(yacc[nt][2] * sc1, yacc[nt][3] * sc1, h, l);
            *(uint32_t*)(smem + OFF_YH + o1) = h;
            *(uint32_t*)(smem + OFF_YL + o1) = l;
        }
    }

    // ---- projection: out[64,256] = Ynorm @ Weff^T, 4 K-chunks of 64 ----
    float pacc[8][4];
#pragma unroll
    for (int i = 0; i < 8; i++)
#pragma unroll
        for (int j = 0; j < 4; j++) pacc[i][j] = 0.f;

    const int ar = mw * 16 + (lane & 15);
    for (int ch = 0; ch < 4; ch++) {
        __syncthreads();
        {   // W chunk: tid>>8 selects hi/lo array, tid&255 = dout row (128B)
            const int which = tid >> 8;
            const int dout = tid & 255;
            const unsigned short* wsrc = (which ? g_Wl : g_Wh) + (size_t)dout * 256 + ch * 64;
            const uint32_t wbase = which ? (uint32_t)OFF_WL : (uint32_t)OFF_WH;
#pragma unroll
            for (int s = 0; s < 8; s++) {
                const uint32_t off = (uint32_t)dout * 128u + SWZ(dout, s * 16);
                cp16(sb + wbase + off, wsrc + s * 8);
            }
            CP_COMMIT();
            CP_WAIT0();
        }
        __syncthreads();

#pragma unroll
        for (int ks = 0; ks < 4; ks++) {
            const uint32_t acb = (uint32_t)(ch * 128 + ks * 32 + ((lane >> 4) << 4));
            const uint32_t aoff = (uint32_t)ar * 512u + SWZ(ar, acb);
            uint32_t yh0, yh1, yh2, yh3, yl0, yl1, yl2, yl3;
            ldsm4(sb + OFF_YH + aoff, yh0, yh1, yh2, yh3);
            ldsm4(sb + OFF_YL + aoff, yl0, yl1, yl2, yl3);
#pragma unroll
            for (int pt = 0; pt < 4; pt++) {
                const int dout2 = nw * 64 + pt * 16 + (lane & 7) + ((lane >> 4) << 3);
                const uint32_t kb = (uint32_t)(ks * 32 + (((lane >> 3) & 1) << 4));
                const uint32_t woff = (uint32_t)dout2 * 128u + SWZ(dout2, kb);
                uint32_t wh0, wh1, wh2, wh3, wl0, wl1, wl2, wl3;
                ldsm4(sb + OFF_WH + woff, wh0, wh1, wh2, wh3);
                ldsm4(sb + OFF_WL + woff, wl0, wl1, wl2, wl3);
                mma16816(pacc[2 * pt],     yh0, yh1, yh2, yh3, wh0, wh1);
                mma16816(pacc[2 * pt],     yh0, yh1, yh2, yh3, wl0, wl1);
                mma16816(pacc[2 * pt],     yl0, yl1, yl2, yl3, wh0, wh1);
                mma16816(pacc[2 * pt + 1], yh0, yh1, yh2, yh3, wh2, wh3);
                mma16816(pacc[2 * pt + 1], yh0, yh1, yh2, yh3, wl2, wl3);
                mma16816(pacc[2 * pt + 1], yl0, yl1, yl2, yl3, wh2, wh3);
            }
        }
    }

    // ---- write output ----
    {
        float* ob = out + (size_t)b * SEQ * DIM;
#pragma unroll
        for (int nt = 0; nt < 8; nt++) {
            const int col = nw * 64 + nt * 8 + (lane & 3) * 2;
            *(float2*)(ob + (size_t)qg0 * DIM + col) = make_float2(pacc[nt][0], pacc[nt][1]);
            *(float2*)(ob + (size_t)qg1 * DIM + col) = make_float2(pacc[nt][2], pacc[nt][3]);
        }
    }
}

// ---------------------------------------------------------------------------
extern "C" void kernel_launch(void* const* d_in, const int* in_sizes, int n_in,
                              void* d_out, int out_size) {
    const float *e = nullptr, *p = nullptr, *wo = nullptr;
    for (int i = 0; i < n_in; i++) {
        if      (in_sizes[i] == NE)              e  = (const float*)d_in[i];
        else if (in_sizes[i] == NP)              p  = (const float*)d_in[i];
        else if (in_sizes[i] == DIM * DIM * HEADS) wo = (const float*)d_in[i];
    }

    cudaFuncSetAttribute(attn_kernel, cudaFuncAttributeMaxDynamicSharedMemorySize, SMEM_TOTAL);

    split_pe_kernel<<<(NP + 255) / 256, 256>>>(p, e);
    weff_kernel<<<DIM * DIM / 256, 256>>>(wo);
    attn_kernel<<<dim3(SEQ / BQ, BATCH), NTHR, SMEM_TOTAL>>>((float*)d_out);
}

// round 7
// speedup vs baseline: 6.1763x; 1.4509x over previous
#include <cuda_runtime.h>
#include <cuda_bf16.h>
#include <cstdint>

#define BATCH 8
#define SEQ   2048
#define DIM   256
#define HEADS 8
#define BQ 64
#define BK 64
#define NTHR 512
#define NP (BATCH * (SEQ + 1) * DIM)
#define NE (BATCH * SEQ * DIM)

// ---- smem byte offsets ----
#define OFF_QH 0
#define OFF_QL 32768
#define OFF_KH 65536
#define OFF_KL 98304
#define OFF_EH 131072
#define OFF_EL 163840
#define OFF_PH 196608
#define OFF_PL 204800
#define OFF_RS 212992
#define SMEM_TOTAL (OFF_RS + 256)
// reuse after key loop:
#define OFF_YH OFF_QH
#define OFF_YL OFF_QL
#define OFF_WH OFF_KH
#define OFF_WL OFF_KL

// pre-split operands (bf16 bits as ushort)
__device__ __align__(16) unsigned short g_ph[NP];
__device__ __align__(16) unsigned short g_pl[NP];
__device__ __align__(16) unsigned short g_eh[NE];
__device__ __align__(16) unsigned short g_el[NE];
__device__ __align__(16) unsigned short g_Wh[DIM * DIM];
__device__ __align__(16) unsigned short g_Wl[DIM * DIM];

// ---- helpers ----
__device__ __forceinline__ uint32_t smem_u32(const void* p) {
    uint32_t a;
    asm("{ .reg .u64 t; cvta.to.shared.u64 t, %1; cvt.u32.u64 %0, t; }" : "=r"(a) : "l"(p));
    return a;
}
__device__ __forceinline__ void cp16(uint32_t dst, const void* src) {
    asm volatile("cp.async.cg.shared.global [%0], [%1], 16;" :: "r"(dst), "l"(src));
}
#define CP_COMMIT() asm volatile("cp.async.commit_group;" ::: "memory")
#define CP_WAIT0()  asm volatile("cp.async.wait_group 0;" ::: "memory")
#define CP_WAIT1()  asm volatile("cp.async.wait_group 1;" ::: "memory")

__device__ __forceinline__ void ldsm4(uint32_t addr, uint32_t& r0, uint32_t& r1, uint32_t& r2, uint32_t& r3) {
    asm volatile("ldmatrix.sync.aligned.m8n8.x4.shared.b16 {%0,%1,%2,%3}, [%4];"
                 : "=r"(r0), "=r"(r1), "=r"(r2), "=r"(r3) : "r"(addr));
}
__device__ __forceinline__ void ldsm4t(uint32_t addr, uint32_t& r0, uint32_t& r1, uint32_t& r2, uint32_t& r3) {
    asm volatile("ldmatrix.sync.aligned.m8n8.x4.trans.shared.b16 {%0,%1,%2,%3}, [%4];"
                 : "=r"(r0), "=r"(r1), "=r"(r2), "=r"(r3) : "r"(addr));
}
__device__ __forceinline__ void mma16816(float* c, uint32_t a0, uint32_t a1, uint32_t a2, uint32_t a3,
                                         uint32_t b0, uint32_t b1) {
    asm volatile("mma.sync.aligned.m16n8k16.row.col.f32.bf16.bf16.f32 "
                 "{%0,%1,%2,%3}, {%4,%5,%6,%7}, {%8,%9}, {%0,%1,%2,%3};"
                 : "+f"(c[0]), "+f"(c[1]), "+f"(c[2]), "+f"(c[3])
                 : "r"(a0), "r"(a1), "r"(a2), "r"(a3), "r"(b0), "r"(b1));
}
__device__ __forceinline__ void split2(float x0, float x1, unsigned& hp, unsigned& lp) {
    __nv_bfloat16 h0 = __float2bfloat16_rn(x0);
    __nv_bfloat16 h1 = __float2bfloat16_rn(x1);
    __nv_bfloat16 l0 = __float2bfloat16_rn(x0 - __bfloat162float(h0));
    __nv_bfloat16 l1 = __float2bfloat16_rn(x1 - __bfloat162float(h1));
    hp = (unsigned)__bfloat16_as_ushort(h0) | ((unsigned)__bfloat16_as_ushort(h1) << 16);
    lp = (unsigned)__bfloat16_as_ushort(l0) | ((unsigned)__bfloat16_as_ushort(l1) << 16);
}
#define SWZ(row, colb) ((uint32_t)(colb) ^ (((uint32_t)(row) & 7u) << 4))

// ---------------------------------------------------------------------------
// Precompute: split p/e into hi/lo bf16 (vectorized x4)
// ---------------------------------------------------------------------------
__global__ void split_pe_kernel(const float4* __restrict__ p4, const float4* __restrict__ e4) {
    int i = blockIdx.x * blockDim.x + threadIdx.x;
    if (i < NP / 4) {
        float4 v = p4[i];
        unsigned h01, l01, h23, l23;
        split2(v.x, v.y, h01, l01);
        split2(v.z, v.w, h23, l23);
        *(uint2*)(g_ph + 4 * (size_t)i) = make_uint2(h01, h23);
        *(uint2*)(g_pl + 4 * (size_t)i) = make_uint2(l01, l23);
    }
    if (i < NE / 4) {
        float4 v = e4[i];
        unsigned h01, l01, h23, l23;
        split2(v.x, v.y, h01, l01);
        split2(v.z, v.w, h23, l23);
        *(uint2*)(g_eh + 4 * (size_t)i) = make_uint2(h01, h23);
        *(uint2*)(g_el + 4 * (size_t)i) = make_uint2(l01, l23);
    }
}

// W_eff[n][k] = sum_h W_o[n, h*DIM + k], split
__global__ void weff_kernel(const float* __restrict__ Wo) {
    int t = blockIdx.x * blockDim.x + threadIdx.x;
    int dout = t >> 8, din = t & 255;
    float s = 0.f;
#pragma unroll
    for (int h = 0; h < HEADS; h++)
        s += Wo[(size_t)dout * (DIM * HEADS) + h * DIM + din];
    __nv_bfloat16 hh = __float2bfloat16_rn(s);
    g_Wh[t] = __bfloat16_as_ushort(hh);
    g_Wl[t] = __bfloat16_as_ushort(__float2bfloat16_rn(s - __bfloat162float(hh)));
}

// ---------------------------------------------------------------------------
// Fused attention + projection, mma.sync bf16x3, paired q-tiles for perfect
// balance: CTA (bx, b) processes qt = 31-bx then qt = bx  (33 key-tile units
// each). 512 threads (16 warps: 4 m-warps x 4 n-warps). K/E loads pipelined
// via two cp.async groups.
// ---------------------------------------------------------------------------
__global__ __launch_bounds__(NTHR, 1)
void attn_kernel(float* __restrict__ out) {
    extern __shared__ char smem[];
    const uint32_t sb = smem_u32(smem);
    const int tid  = threadIdx.x;
    const int lane = tid & 31;
    const int wid  = tid >> 5;
    const int mw   = wid & 3;
    const int nw   = wid >> 2;
    const int b    = blockIdx.y;
    const unsigned short* ph = g_ph + (size_t)b * (SEQ + 1) * DIM;
    const unsigned short* pl = g_pl + (size_t)b * (SEQ + 1) * DIM;
    const unsigned short* eh = g_eh + (size_t)b * SEQ * DIM;
    const unsigned short* el = g_el + (size_t)b * SEQ * DIM;
    float* rowsum = (float*)(smem + OFF_RS);

    const int row0 = mw * 16 + (lane >> 2);
    const int ar   = mw * 16 + (lane & 15);
    const int key  = nw * 16 + (lane & 7) + ((lane >> 4) << 3);
    const int ldr  = tid >> 3;        // loader row 0..63
    const int lds0 = tid & 7;         // loader segment

    for (int pass = 0; pass < 2; pass++) {
        const int qt = pass ? (int)blockIdx.x : 31 - (int)blockIdx.x;
        const int q0 = qt * BQ;
        const int qg0 = q0 + row0, qg1 = qg0 + 8;
        if (tid < BQ) rowsum[tid] = 0.f;

        // ---- prologue: Q + K(0) (group 1), E(0) (group 2) ----
        {
            const unsigned short* qh = ph + (size_t)(q0 + ldr + 1) * DIM;
            const unsigned short* ql = pl + (size_t)(q0 + ldr + 1) * DIM;
            const unsigned short* kh = ph + (size_t)ldr * DIM;
            const unsigned short* kl = pl + (size_t)ldr * DIM;
#pragma unroll
            for (int j = 0; j < 4; j++) {
                const int seg = lds0 + j * 8;
                const uint32_t off = (uint32_t)ldr * 512u + SWZ(ldr, seg * 16);
                cp16(sb + OFF_QH + off, qh + seg * 8);
                cp16(sb + OFF_QL + off, ql + seg * 8);
                cp16(sb + OFF_KH + off, kh + seg * 8);
                cp16(sb + OFF_KL + off, kl + seg * 8);
            }
            CP_COMMIT();
            const unsigned short* vh = eh + (size_t)ldr * DIM;
            const unsigned short* vl = el + (size_t)ldr * DIM;
#pragma unroll
            for (int j = 0; j < 4; j++) {
                const int seg = lds0 + j * 8;
                const uint32_t off = (uint32_t)ldr * 512u + SWZ(ldr, seg * 16);
                cp16(sb + OFF_EH + off, vh + seg * 8);
                cp16(sb + OFF_EL + off, vl + seg * 8);
            }
            CP_COMMIT();
        }
        CP_WAIT1();              // Q + K(0) landed; E(0) in flight
        __syncthreads();

        float yacc[8][4];
#pragma unroll
        for (int i = 0; i < 8; i++)
#pragma unroll
            for (int j = 0; j < 4; j++) yacc[i][j] = 0.f;
        float rs0 = 0.f, rs1 = 0.f;

        // ---- key-tile loop (pipelined) ----
        for (int kt = 0; kt <= qt; kt++) {
            const int k0 = kt * BK;

            // S GEMM: warp tile 16 rows x 16 keys
            float sacc[2][4];
#pragma unroll
            for (int i = 0; i < 2; i++)
#pragma unroll
                for (int j = 0; j < 4; j++) sacc[i][j] = 0.f;
#pragma unroll
            for (int ks = 0; ks < 16; ks++) {
                const uint32_t acb = (uint32_t)(ks * 32 + ((lane >> 4) << 4));
                const uint32_t aoff = (uint32_t)ar * 512u + SWZ(ar, acb);
                uint32_t qh0, qh1, qh2, qh3, ql0, ql1, ql2, ql3;
                ldsm4(sb + OFF_QH + aoff, qh0, qh1, qh2, qh3);
                ldsm4(sb + OFF_QL + aoff, ql0, ql1, ql2, ql3);
                const uint32_t kb = (uint32_t)(ks * 32 + (((lane >> 3) & 1) << 4));
                const uint32_t koff = (uint32_t)key * 512u + SWZ(key, kb);
                uint32_t kh0, kh1, kh2, kh3, kl0, kl1, kl2, kl3;
                ldsm4(sb + OFF_KH + koff, kh0, kh1, kh2, kh3);
                ldsm4(sb + OFF_KL + koff, kl0, kl1, kl2, kl3);
                mma16816(sacc[0], qh0, qh1, qh2, qh3, kh0, kh1);
                mma16816(sacc[0], qh0, qh1, qh2, qh3, kl0, kl1);
                mma16816(sacc[0], ql0, ql1, ql2, ql3, kh0, kh1);
                mma16816(sacc[1], qh0, qh1, qh2, qh3, kh2, kh3);
                mma16816(sacc[1], qh0, qh1, qh2, qh3, kl2, kl3);
                mma16816(sacc[1], ql0, ql1, ql2, ql3, kh2, kh3);
            }
            __syncthreads();     // all warps done reading K(kt)

            // prefetch K(kt+1) (overlaps epilogue + AV)
            if (kt < qt) {
                const unsigned short* kh = ph + (size_t)(k0 + BK + ldr) * DIM;
                const unsigned short* kl = pl + (size_t)(k0 + BK + ldr) * DIM;
#pragma unroll
                for (int j = 0; j < 4; j++) {
                    const int seg = lds0 + j * 8;
                    const uint32_t off = (uint32_t)ldr * 512u + SWZ(ldr, seg * 16);
                    cp16(sb + OFF_KH + off, kh + seg * 8);
                    cp16(sb + OFF_KL + off, kl + seg * 8);
                }
            }
            CP_COMMIT();

            // epilogue: scale/clip/mask/exp; rowsum partials; P -> smem
#pragma unroll
            for (int nt = 0; nt < 2; nt++) {
                const int colL = nw * 16 + nt * 8 + (lane & 3) * 2;
                const int kgl = k0 + colL;
                float s00 = fminf(10.f, fmaxf(-10.f, sacc[nt][0] * 0.0625f));
                float s01 = fminf(10.f, fmaxf(-10.f, sacc[nt][1] * 0.0625f));
                float s10 = fminf(10.f, fmaxf(-10.f, sacc[nt][2] * 0.0625f));
                float s11 = fminf(10.f, fmaxf(-10.f, sacc[nt][3] * 0.0625f));
                float w00 = (kgl     <= qg0) ? __expf(s00) : 0.f;
                float w01 = (kgl + 1 <= qg0) ? __expf(s01) : 0.f;
                float w10 = (kgl     <= qg1) ? __expf(s10) : 0.f;
                float w11 = (kgl + 1 <= qg1) ? __expf(s11) : 0.f;
                rs0 += w00 + w01;
                rs1 += w10 + w11;
                unsigned h, l;
                uint32_t o0 = (uint32_t)row0 * 128u + SWZ(row0, colL * 2);
                split2(w00, w01, h, l);
                *(uint32_t*)(smem + OFF_PH + o0) = h;
                *(uint32_t*)(smem + OFF_PL + o0) = l;
                uint32_t o1 = (uint32_t)(row0 + 8) * 128u + SWZ(row0 + 8, colL * 2);
                split2(w10, w11, h, l);
                *(uint32_t*)(smem + OFF_PH + o1) = h;
                *(uint32_t*)(smem + OFF_PL + o1) = l;
            }
            CP_WAIT1();          // E(kt) complete (K(kt+1) may still be in flight)
            __syncthreads();     // P + E visible to all

            // AV GEMM: warp tile 16 rows x 64 dims
#pragma unroll
            for (int ks = 0; ks < 4; ks++) {
                const uint32_t acb = (uint32_t)(ks * 32 + ((lane >> 4) << 4));
                const uint32_t aoff = (uint32_t)ar * 128u + SWZ(ar, acb);
                uint32_t ph0, ph1, ph2, ph3, pl0, pl1, pl2, pl3;
                ldsm4(sb + OFF_PH + aoff, ph0, ph1, ph2, ph3);
                ldsm4(sb + OFF_PL + aoff, pl0, pl1, pl2, pl3);
                const int key2 = ks * 16 + (lane & 15);
#pragma unroll
                for (int grp = 0; grp < 4; grp++) {
                    const uint32_t dcb = (uint32_t)((nw * 64 + grp * 16 + ((lane >> 4) << 3)) * 2);
                    const uint32_t eoff = (uint32_t)key2 * 512u + SWZ(key2, dcb);
                    uint32_t eh0, eh1, eh2, eh3, el0, el1, el2, el3;
                    ldsm4t(sb + OFF_EH + eoff, eh0, eh1, eh2, eh3);
                    ldsm4t(sb + OFF_EL + eoff, el0, el1, el2, el3);
                    mma16816(yacc[2 * grp],     ph0, ph1, ph2, ph3, eh0, eh1);
                    mma16816(yacc[2 * grp],     ph0, ph1, ph2, ph3, el0, el1);
                    mma16816(yacc[2 * grp],     pl0, pl1, pl2, pl3, eh0, eh1);
                    mma16816(yacc[2 * grp + 1], ph0, ph1, ph2, ph3, eh2, eh3);
                    mma16816(yacc[2 * grp + 1], ph0, ph1, ph2, ph3, el2, el3);
                    mma16816(yacc[2 * grp + 1], pl0, pl1, pl2, pl3, eh2, eh3);
                }
            }
            __syncthreads();     // all warps done reading E(kt)

            // prefetch E(kt+1) (overlaps next S GEMM + epilogue)
            if (kt < qt) {
                const unsigned short* vh = eh + (size_t)(k0 + BK + ldr) * DIM;
                const unsigned short* vl = el + (size_t)(k0 + BK + ldr) * DIM;
#pragma unroll
                for (int j = 0; j < 4; j++) {
                    const int seg = lds0 + j * 8;
                    const uint32_t off = (uint32_t)ldr * 512u + SWZ(ldr, seg * 16);
                    cp16(sb + OFF_EH + off, vh + seg * 8);
                    cp16(sb + OFF_EL + off, vl + seg * 8);
                }
            }
            CP_COMMIT();
            CP_WAIT1();          // K(kt+1) complete (E(kt+1) may still be in flight)
            __syncthreads();
        }

        // ---- rowsum reduce ----
        rs0 += __shfl_xor_sync(0xffffffffu, rs0, 1);
        rs0 += __shfl_xor_sync(0xffffffffu, rs0, 2);
        rs1 += __shfl_xor_sync(0xffffffffu, rs1, 1);
        rs1 += __shfl_xor_sync(0xffffffffu, rs1, 2);
        if ((lane & 3) == 0) {
            atomicAdd(&rowsum[row0], rs0);
            atomicAdd(&rowsum[row0 + 8], rs1);
        }
        __syncthreads();

        // ---- normalize Y, split bf16 to smem (reuse Q area) ----
        {
            const float sc0 = 1.f / (rowsum[row0] * (float)(qg0 + 1));
            const float sc1 = 1.f / (rowsum[row0 + 8] * (float)(qg1 + 1));
#pragma unroll
            for (int nt = 0; nt < 8; nt++) {
                const int col = nw * 64 + nt * 8 + (lane & 3) * 2;
                unsigned h, l;
                uint32_t o0 = (uint32_t)row0 * 512u + SWZ(row0, col * 2);
                split2(yacc[nt][0] * sc0, yacc[nt][1] * sc0, h, l);
                *(uint32_t*)(smem + OFF_YH + o0) = h;
                *(uint32_t*)(smem + OFF_YL + o0) = l;
                uint32_t o1 = (uint32_t)(row0 + 8) * 512u + SWZ(row0 + 8, col * 2);
                split2(yacc[nt][2] * sc1, yacc[nt][3] * sc1, h, l);
                *(uint32_t*)(smem + OFF_YH + o1) = h;
                *(uint32_t*)(smem + OFF_YL + o1) = l;
            }
        }

        // ---- projection: out[64,256] = Ynorm @ Weff^T, 4 K-chunks of 64 ----
        float pacc[8][4];
#pragma unroll
        for (int i = 0; i < 8; i++)
#pragma unroll
            for (int j = 0; j < 4; j++) pacc[i][j] = 0.f;

        for (int ch = 0; ch < 4; ch++) {
            __syncthreads();
            {
                const int which = tid >> 8;
                const int dout = tid & 255;
                const unsigned short* wsrc = (which ? g_Wl : g_Wh) + (size_t)dout * 256 + ch * 64;
                const uint32_t wbase = which ? (uint32_t)OFF_WL : (uint32_t)OFF_WH;
#pragma unroll
                for (int s = 0; s < 8; s++) {
                    const uint32_t off = (uint32_t)dout * 128u + SWZ(dout, s * 16);
                    cp16(sb + wbase + off, wsrc + s * 8);
                }
                CP_COMMIT();
                CP_WAIT0();
            }
            __syncthreads();

#pragma unroll
            for (int ks = 0; ks < 4; ks++) {
                const uint32_t acb = (uint32_t)(ch * 128 + ks * 32 + ((lane >> 4) << 4));
                const uint32_t aoff = (uint32_t)ar * 512u + SWZ(ar, acb);
                uint32_t yh0, yh1, yh2, yh3, yl0, yl1, yl2, yl3;
                ldsm4(sb + OFF_YH + aoff, yh0, yh1, yh2, yh3);
                ldsm4(sb + OFF_YL + aoff, yl0, yl1, yl2, yl3);
#pragma unroll
                for (int pt = 0; pt < 4; pt++) {
                    const int dout2 = nw * 64 + pt * 16 + (lane & 7) + ((lane >> 4) << 3);
                    const uint32_t kb = (uint32_t)(ks * 32 + (((lane >> 3) & 1) << 4));
                    const uint32_t woff = (uint32_t)dout2 * 128u + SWZ(dout2, kb);
                    uint32_t wh0, wh1, wh2, wh3, wl0, wl1, wl2, wl3;
                    ldsm4(sb + OFF_WH + woff, wh0, wh1, wh2, wh3);
                    ldsm4(sb + OFF_WL + woff, wl0, wl1, wl2, wl3);
                    mma16816(pacc[2 * pt],     yh0, yh1, yh2, yh3, wh0, wh1);
                    mma16816(pacc[2 * pt],     yh0, yh1, yh2, yh3, wl0, wl1);
                    mma16816(pacc[2 * pt],     yl0, yl1, yl2, yl3, wh0, wh1);
                    mma16816(pacc[2 * pt + 1], yh0, yh1, yh2, yh3, wh2, wh3);
                    mma16816(pacc[2 * pt + 1], yh0, yh1, yh2, yh3, wl2, wl3);
                    mma16816(pacc[2 * pt + 1], yl0, yl1, yl2, yl3, wh2, wh3);
                }
            }
        }

        // ---- write output ----
        {
            float* ob = out + (size_t)b * SEQ * DIM;
#pragma unroll
            for (int nt = 0; nt < 8; nt++) {
                const int col = nw * 64 + nt * 8 + (lane & 3) * 2;
                *(float2*)(ob + (size_t)qg0 * DIM + col) = make_float2(pacc[nt][0], pacc[nt][1]);
                *(float2*)(ob + (size_t)qg1 * DIM + col) = make_float2(pacc[nt][2], pacc[nt][3]);
            }
        }
        __syncthreads();   // pass isolation (smem reuse)
    }
}

// ---------------------------------------------------------------------------
extern "C" void kernel_launch(void* const* d_in, const int* in_sizes, int n_in,
                              void* d_out, int out_size) {
    const float *e = nullptr, *p = nullptr, *wo = nullptr;
    for (int i = 0; i < n_in; i++) {
        if      (in_sizes[i] == NE)                e  = (const float*)d_in[i];
        else if (in_sizes[i] == NP)                p  = (const float*)d_in[i];
        else if (in_sizes[i] == DIM * DIM * HEADS) wo = (const float*)d_in[i];
    }

    cudaFuncSetAttribute(attn_kernel, cudaFuncAttributeMaxDynamicSharedMemorySize, SMEM_TOTAL);

    split_pe_kernel<<<(NP / 4 + 255) / 256, 256>>>((const float4*)p, (const float4*)e);
    weff_kernel<<<DIM * DIM / 256, 256>>>(wo);
    attn_kernel<<<dim3(16, BATCH), NTHR, SMEM_TOTAL>>>((float*)d_out);
}